// round 1
// baseline (speedup 1.0000x reference)
#include <cuda_runtime.h>
#include <math.h>

#define BB 4
#define CC 512
#define HW 4096
#define GROUPS 32
#define GSIZE 16  // channels per group

// ---------------- scratch (device globals: allocation-free) ----------------
__device__ float g_hn[(size_t)BB * CC * HW];
__device__ float g_q [(size_t)BB * CC * HW];
__device__ float g_k [(size_t)BB * CC * HW];
__device__ float g_v [(size_t)BB * CC * HW];
__device__ float g_s [(size_t)BB * HW * HW];   // 256 MB attention scores / weights
__device__ float g_h [(size_t)BB * CC * HW];

// ---------------- GroupNorm ----------------
// grid = BB*GROUPS blocks, 256 threads. Each block: one (batch, group) =
// 16 channels x 4096 spatial = 65536 floats. Two passes, Welford-free:
// per-thread partial sum/sumsq (256 elems each, fp32 ok), block reduce.
__global__ __launch_bounds__(256) void gn_kernel(
    const float* __restrict__ x, const float* __restrict__ gamma,
    const float* __restrict__ beta, float* __restrict__ out)
{
    const int b = blockIdx.x >> 5;
    const int g = blockIdx.x & 31;
    const size_t base = ((size_t)b * CC + (size_t)g * GSIZE) * HW;
    const int LEN4 = (GSIZE * HW) / 4;  // 16384 float4
    const float4* __restrict__ xin = (const float4*)(x + base);

    float s = 0.f, s2 = 0.f;
    for (int i = threadIdx.x; i < LEN4; i += 256) {
        float4 t = xin[i];
        s  += t.x + t.y + t.z + t.w;
        s2 += t.x * t.x + t.y * t.y + t.z * t.z + t.w * t.w;
    }

    __shared__ float wr1[8], wr2[8];
    __shared__ float s_mu, s_rstd;
    for (int o = 16; o; o >>= 1) {
        s  += __shfl_xor_sync(0xffffffffu, s,  o);
        s2 += __shfl_xor_sync(0xffffffffu, s2, o);
    }
    const int warp = threadIdx.x >> 5, lane = threadIdx.x & 31;
    if (lane == 0) { wr1[warp] = s; wr2[warp] = s2; }
    __syncthreads();
    if (threadIdx.x == 0) {
        float ts = 0.f, ts2 = 0.f;
        #pragma unroll
        for (int i = 0; i < 8; i++) { ts += wr1[i]; ts2 += wr2[i]; }
        const float inv_n = 1.0f / (float)(GSIZE * HW);
        float mu  = ts * inv_n;
        float var = ts2 * inv_n - mu * mu;
        s_mu = mu;
        s_rstd = 1.0f / sqrtf(var + 1e-6f);
    }
    __syncthreads();
    const float mu = s_mu, rstd = s_rstd;

    float4* __restrict__ o4 = (float4*)(out + base);
    for (int i = threadIdx.x; i < LEN4; i += 256) {
        float4 t = xin[i];
        const int c = g * GSIZE + ((i * 4) >> 12);  // 4096 elems per channel
        const float ga = gamma[c] * rstd, be = beta[c];
        t.x = (t.x - mu) * ga + be;
        t.y = (t.y - mu) * ga + be;
        t.z = (t.z - mu) * ga + be;
        t.w = (t.w - mu) * ga + be;
        o4[i] = t;
    }
}

// ---------------- Generic tiled SGEMM ----------------
// C[m,n] = scale * sum_k opA(A)[m,k] * opB(B)[k,n]  (+ bias/quant/resid per MODE)
// TA: A stored [K,M] (use A^T). TB: B stored [N,K] (use B^T).
// Leading dims: A normal lda=K, A^T lda=M, B normal ldb=N, B^T ldb=K, C ldc=N.
// MODE 0: += bias[row]; fake_quant(delta, zp, 256)
// MODE 1: scale only
// MODE 2: plain
// MODE 3: += bias[row]; += resid
// 128x128 block tile, 256 threads, 8x8 per thread, K-tile 8.
template<bool TA, bool TB, int MODE>
__global__ __launch_bounds__(256) void gemm_k(
    const float* __restrict__ A, const float* __restrict__ B, float* __restrict__ C,
    int M, int N, int K,
    size_t sA, size_t sB, size_t sC,
    const float* __restrict__ bias,
    const float* __restrict__ resid, size_t sR,
    const float* __restrict__ d_delta, const float* __restrict__ d_zp,
    float scale)
{
    A += (size_t)blockIdx.z * sA;
    B += (size_t)blockIdx.z * sB;
    C += (size_t)blockIdx.z * sC;
    const int bm = blockIdx.y * 128;
    const int bn = blockIdx.x * 128;
    const int tid = threadIdx.x;
    const int ty = tid >> 4;   // 0..15
    const int tx = tid & 15;   // 0..15

    __shared__ float As[8][128];
    __shared__ float Bs[8][128];

    float acc[8][8];
    #pragma unroll
    for (int i = 0; i < 8; i++)
        #pragma unroll
        for (int j = 0; j < 8; j++) acc[i][j] = 0.f;

    for (int k0 = 0; k0 < K; k0 += 8) {
        if (TA) {
            const int k = tid >> 5, m = (tid & 31) << 2;
            float4 t = *(const float4*)(A + (size_t)(k0 + k) * M + bm + m);
            *(float4*)&As[k][m] = t;
        } else {
            const int m = tid >> 1, k = (tid & 1) << 2;
            float4 t = *(const float4*)(A + (size_t)(bm + m) * K + k0 + k);
            As[k + 0][m] = t.x; As[k + 1][m] = t.y;
            As[k + 2][m] = t.z; As[k + 3][m] = t.w;
        }
        if (TB) {
            const int n = tid >> 1, k = (tid & 1) << 2;
            float4 t = *(const float4*)(B + (size_t)(bn + n) * K + k0 + k);
            Bs[k + 0][n] = t.x; Bs[k + 1][n] = t.y;
            Bs[k + 2][n] = t.z; Bs[k + 3][n] = t.w;
        } else {
            const int k = tid >> 5, n = (tid & 31) << 2;
            float4 t = *(const float4*)(B + (size_t)(k0 + k) * N + bn + n);
            *(float4*)&Bs[k][n] = t;
        }
        __syncthreads();
        #pragma unroll
        for (int kk = 0; kk < 8; kk++) {
            float a[8], bf[8];
            *(float4*)&a[0]  = *(float4*)&As[kk][ty * 8];
            *(float4*)&a[4]  = *(float4*)&As[kk][ty * 8 + 4];
            *(float4*)&bf[0] = *(float4*)&Bs[kk][tx * 8];
            *(float4*)&bf[4] = *(float4*)&Bs[kk][tx * 8 + 4];
            #pragma unroll
            for (int i = 0; i < 8; i++)
                #pragma unroll
                for (int j = 0; j < 8; j++)
                    acc[i][j] += a[i] * bf[j];
        }
        __syncthreads();
    }

    float delta = 1.f, zp = 0.f, invd = 1.f;
    if (MODE == 0) { delta = *d_delta; zp = *d_zp; invd = 1.f / delta; }

    #pragma unroll
    for (int i = 0; i < 8; i++) {
        const int row = bm + ty * 8 + i;
        const float bs = (MODE == 0 || MODE == 3) ? bias[row] : 0.f;
        float* crow = C + (size_t)row * N + bn + tx * 8;
        const float* rrow = (MODE == 3)
            ? (resid + (size_t)blockIdx.z * sR + (size_t)row * N + bn + tx * 8)
            : nullptr;
        float out[8];
        #pragma unroll
        for (int j = 0; j < 8; j++) {
            float v = acc[i][j] * scale + bs;
            if (MODE == 0) {
                float q = rintf(v * invd) + zp;       // round-half-to-even, matches jnp.round
                q = fminf(fmaxf(q, 0.f), 255.f);
                v = (q - zp) * delta;
            }
            if (MODE == 3) v += rrow[j];
            out[j] = v;
        }
        *(float4*)&crow[0] = *(float4*)&out[0];
        *(float4*)&crow[4] = *(float4*)&out[4];
    }
}

// ---------------- softmax (over last axis) + fake_quant (zp=0) ----------------
// One block per row of 4096; 16 elems per thread in registers.
__global__ __launch_bounds__(256) void softmax_quant_k(
    float* __restrict__ S, const float* __restrict__ d_dw)
{
    float4* __restrict__ r4 = (float4*)(S + (size_t)blockIdx.x * HW);
    const int tid = threadIdx.x;
    float4 v[4];
    #pragma unroll
    for (int u = 0; u < 4; u++) v[u] = r4[tid + 256 * u];

    float mx = -3.0e38f;
    #pragma unroll
    for (int u = 0; u < 4; u++)
        mx = fmaxf(mx, fmaxf(fmaxf(v[u].x, v[u].y), fmaxf(v[u].z, v[u].w)));

    __shared__ float wr[8];
    __shared__ float bcast;
    for (int o = 16; o; o >>= 1) mx = fmaxf(mx, __shfl_xor_sync(0xffffffffu, mx, o));
    const int warp = tid >> 5, lane = tid & 31;
    if (lane == 0) wr[warp] = mx;
    __syncthreads();
    if (tid == 0) {
        float m = wr[0];
        #pragma unroll
        for (int i = 1; i < 8; i++) m = fmaxf(m, wr[i]);
        bcast = m;
    }
    __syncthreads();
    mx = bcast;

    float sum = 0.f;
    #pragma unroll
    for (int u = 0; u < 4; u++) {
        v[u].x = expf(v[u].x - mx);
        v[u].y = expf(v[u].y - mx);
        v[u].z = expf(v[u].z - mx);
        v[u].w = expf(v[u].w - mx);
        sum += v[u].x + v[u].y + v[u].z + v[u].w;
    }
    for (int o = 16; o; o >>= 1) sum += __shfl_xor_sync(0xffffffffu, sum, o);
    __syncthreads();              // protect wr reuse
    if (lane == 0) wr[warp] = sum;
    __syncthreads();
    if (tid == 0) {
        float t = 0.f;
        #pragma unroll
        for (int i = 0; i < 8; i++) t += wr[i];
        bcast = t;
    }
    __syncthreads();
    const float inv = 1.0f / bcast;
    const float dw = *d_dw;
    const float invdw = 1.0f / dw;

    #pragma unroll
    for (int u = 0; u < 4; u++) {
        float* p = (float*)&v[u];
        #pragma unroll
        for (int e = 0; e < 4; e++) {
            float w = p[e] * inv;
            float q = fminf(fmaxf(rintf(w * invdw), 0.f), 255.f);
            p[e] = q * dw;   // zp = 0 (always_zero)
        }
        r4[tid + 256 * u] = v[u];
    }
}

// ---------------- launch ----------------
extern "C" void kernel_launch(void* const* d_in, const int* in_sizes, int n_in,
                              void* d_out, int out_size)
{
    const float* x     = (const float*)d_in[0];
    const float* gamma = (const float*)d_in[1];
    const float* beta  = (const float*)d_in[2];
    const float* wq    = (const float*)d_in[3];
    const float* bq    = (const float*)d_in[4];
    const float* wk    = (const float*)d_in[5];
    const float* bk    = (const float*)d_in[6];
    const float* wv    = (const float*)d_in[7];
    const float* bv    = (const float*)d_in[8];
    const float* wp    = (const float*)d_in[9];
    const float* bp    = (const float*)d_in[10];
    const float* dq    = (const float*)d_in[11];
    const float* zq    = (const float*)d_in[12];
    const float* dk    = (const float*)d_in[13];
    const float* zk    = (const float*)d_in[14];
    const float* dv    = (const float*)d_in[15];
    const float* zv    = (const float*)d_in[16];
    const float* dw    = (const float*)d_in[17];
    float* out = (float*)d_out;

    float *hn, *q, *k, *v, *s, *h;
    cudaGetSymbolAddress((void**)&hn, g_hn);
    cudaGetSymbolAddress((void**)&q,  g_q);
    cudaGetSymbolAddress((void**)&k,  g_k);
    cudaGetSymbolAddress((void**)&v,  g_v);
    cudaGetSymbolAddress((void**)&s,  g_s);
    cudaGetSymbolAddress((void**)&h,  g_h);

    const size_t CS = (size_t)CC * HW;       // per-batch [C, HW]
    const size_t SS = (size_t)HW * HW;       // per-batch [HW, HW]

    // 1) GroupNorm
    gn_kernel<<<BB * GROUPS, 256>>>(x, gamma, beta, hn);

    // 2) q/k/v = fake_quant(W @ hn + b)
    dim3 gqkv(HW / 128, CC / 128, BB);       // (32, 4, 4)
    gemm_k<false, false, 0><<<gqkv, 256>>>(wq, hn, q, CC, HW, CC,
        0, CS, CS, bq, nullptr, 0, dq, zq, 1.f);
    gemm_k<false, false, 0><<<gqkv, 256>>>(wk, hn, k, CC, HW, CC,
        0, CS, CS, bk, nullptr, 0, dk, zk, 1.f);
    gemm_k<false, false, 0><<<gqkv, 256>>>(wv, hn, v, CC, HW, CC,
        0, CS, CS, bv, nullptr, 0, dv, zv, 1.f);

    // 3) scores[i,j] = (q^T k)[i,j] * C^-0.5   (q,k stored [C, HW])
    dim3 gs(HW / 128, HW / 128, BB);         // (32, 32, 4)
    gemm_k<true, false, 1><<<gs, 256>>>(q, k, s, HW, HW, CC,
        CS, CS, SS, nullptr, nullptr, 0, nullptr, nullptr,
        0.044194173824159216f /* 512^-0.5 */);

    // 4) softmax over j + fake_quant(delta_w, zp=0)
    softmax_quant_k<<<BB * HW, 256>>>(s, dw);

    // 5) h[c,i] = sum_j v[c,j] * w[i,j]   (B^T form)
    gemm_k<false, true, 2><<<gqkv, 256>>>(v, s, h, CC, HW, HW,
        CS, SS, CS, nullptr, nullptr, 0, nullptr, nullptr, 1.f);

    // 6) out = x + (wp @ h + bp)
    gemm_k<false, false, 3><<<gqkv, 256>>>(wp, h, out, CC, HW, CC,
        0, CS, CS, bp, x, CS, nullptr, nullptr, 1.f);
}

// round 2
// speedup vs baseline: 2.1403x; 2.1403x over previous
#include <cuda_runtime.h>
#include <stdint.h>
#include <math.h>

#define BB 4
#define CC 512
#define HW 4096
#define GROUPS 32
#define GSIZE 16

// ---------------- scratch ----------------
__device__ float   g_hn[(size_t)BB * CC * HW];
__device__ float   g_h [(size_t)BB * CC * HW];
__device__ float   g_s [(size_t)BB * HW * HW];   // f32 scores (256MB)
__device__ int8_t  g_q8[(size_t)BB * HW * CC];   // [b][pixel][c]  (A operand of QK^T)
__device__ int8_t  g_k8[(size_t)BB * HW * CC];   // [b][pixel][c]  (B operand of QK^T)
__device__ int8_t  g_v8[(size_t)BB * CC * HW];   // [b][c][pixel]  (A operand of V*W^T)
__device__ uint8_t g_w8[(size_t)BB * HW * HW];   // [b][q][j]      (B operand of V*W^T)

// ---------------- GroupNorm ----------------
__global__ __launch_bounds__(256) void gn_kernel(
    const float* __restrict__ x, const float* __restrict__ gamma,
    const float* __restrict__ beta, float* __restrict__ out)
{
    const int b = blockIdx.x >> 5;
    const int g = blockIdx.x & 31;
    const size_t base = ((size_t)b * CC + (size_t)g * GSIZE) * HW;
    const int LEN4 = (GSIZE * HW) / 4;
    const float4* __restrict__ xin = (const float4*)(x + base);

    float s = 0.f, s2 = 0.f;
    for (int i = threadIdx.x; i < LEN4; i += 256) {
        float4 t = xin[i];
        s  += t.x + t.y + t.z + t.w;
        s2 += t.x * t.x + t.y * t.y + t.z * t.z + t.w * t.w;
    }
    __shared__ float wr1[8], wr2[8];
    __shared__ float s_mu, s_rstd;
    for (int o = 16; o; o >>= 1) {
        s  += __shfl_xor_sync(0xffffffffu, s,  o);
        s2 += __shfl_xor_sync(0xffffffffu, s2, o);
    }
    const int warp = threadIdx.x >> 5, lane = threadIdx.x & 31;
    if (lane == 0) { wr1[warp] = s; wr2[warp] = s2; }
    __syncthreads();
    if (threadIdx.x == 0) {
        float ts = 0.f, ts2 = 0.f;
        #pragma unroll
        for (int i = 0; i < 8; i++) { ts += wr1[i]; ts2 += wr2[i]; }
        const float inv_n = 1.0f / (float)(GSIZE * HW);
        float mu  = ts * inv_n;
        float var = ts2 * inv_n - mu * mu;
        s_mu = mu;
        s_rstd = 1.0f / sqrtf(var + 1e-6f);
    }
    __syncthreads();
    const float mu = s_mu, rstd = s_rstd;

    float4* __restrict__ o4 = (float4*)(out + base);
    for (int i = threadIdx.x; i < LEN4; i += 256) {
        float4 t = xin[i];
        const int c = g * GSIZE + ((i * 4) >> 12);
        const float ga = gamma[c] * rstd, be = beta[c];
        t.x = (t.x - mu) * ga + be;
        t.y = (t.y - mu) * ga + be;
        t.z = (t.z - mu) * ga + be;
        t.w = (t.w - mu) * ga + be;
        o4[i] = t;
    }
}

// ---------------- fp32 SGEMM, C[m,n] = A[m,k] B[k,n] (+epilogues) ----------------
// MODE 0: f32 out, += bias[row], += resid          (output projection)
// MODE 1: s8 out TRANSPOSED [N, M], quant           (q, k)
// MODE 2: s8 out natural [M, N], quant              (v)
template<int MODE>
__global__ __launch_bounds__(256) void gemm_k(
    const float* __restrict__ A, const float* __restrict__ B, void* __restrict__ Cv,
    int M, int N, int K, size_t sB, size_t sC,
    const float* __restrict__ bias,
    const float* __restrict__ resid, size_t sR,
    const float* __restrict__ d_delta, const float* __restrict__ d_zp)
{
    B += (size_t)blockIdx.z * sB;
    const int bm = blockIdx.y * 128;
    const int bn = blockIdx.x * 128;
    const int tid = threadIdx.x;
    const int ty = tid >> 4;
    const int tx = tid & 15;

    __shared__ float As[8][128];
    __shared__ float Bs[8][128];

    float acc[8][8];
    #pragma unroll
    for (int i = 0; i < 8; i++)
        #pragma unroll
        for (int j = 0; j < 8; j++) acc[i][j] = 0.f;

    for (int k0 = 0; k0 < K; k0 += 8) {
        {
            const int m = tid >> 1, k = (tid & 1) << 2;
            float4 t = *(const float4*)(A + (size_t)(bm + m) * K + k0 + k);
            As[k + 0][m] = t.x; As[k + 1][m] = t.y;
            As[k + 2][m] = t.z; As[k + 3][m] = t.w;
        }
        {
            const int k = tid >> 5, n = (tid & 31) << 2;
            float4 t = *(const float4*)(B + (size_t)(k0 + k) * N + bn + n);
            *(float4*)&Bs[k][n] = t;
        }
        __syncthreads();
        #pragma unroll
        for (int kk = 0; kk < 8; kk++) {
            float a[8], bf[8];
            *(float4*)&a[0]  = *(float4*)&As[kk][ty * 8];
            *(float4*)&a[4]  = *(float4*)&As[kk][ty * 8 + 4];
            *(float4*)&bf[0] = *(float4*)&Bs[kk][tx * 8];
            *(float4*)&bf[4] = *(float4*)&Bs[kk][tx * 8 + 4];
            #pragma unroll
            for (int i = 0; i < 8; i++)
                #pragma unroll
                for (int j = 0; j < 8; j++)
                    acc[i][j] += a[i] * bf[j];
        }
        __syncthreads();
    }

    if (MODE == 0) {
        float* C = (float*)Cv + (size_t)blockIdx.z * sC;
        #pragma unroll
        for (int i = 0; i < 8; i++) {
            const int row = bm + ty * 8 + i;
            const float bs = bias[row];
            float* crow = C + (size_t)row * N + bn + tx * 8;
            const float* rrow = resid + (size_t)blockIdx.z * sR + (size_t)row * N + bn + tx * 8;
            float out[8];
            #pragma unroll
            for (int j = 0; j < 8; j++) out[j] = acc[i][j] + bs + rrow[j];
            *(float4*)&crow[0] = *(float4*)&out[0];
            *(float4*)&crow[4] = *(float4*)&out[4];
        }
    } else {
        const float delta = *d_delta;
        const float zp = *d_zp;
        const float invd = 1.0f / delta;
        const int izp = (int)rintf(zp);

        if (MODE == 2) {
            // natural [M, N] s8
            int8_t* C = (int8_t*)Cv + (size_t)blockIdx.z * sC;
            #pragma unroll
            for (int i = 0; i < 8; i++) {
                const int row = bm + ty * 8 + i;
                const float bs = bias[row];
                union { int8_t b[8]; int2 v; } o;
                #pragma unroll
                for (int j = 0; j < 8; j++) {
                    float q = rintf((acc[i][j] + bs) * invd) + zp;
                    q = fminf(fmaxf(q, 0.f), 255.f);
                    o.b[j] = (int8_t)((int)q - izp);
                }
                *(int2*)(C + (size_t)row * N + bn + tx * 8) = o.v;
            }
        } else {
            // transposed [N, M] s8 via smem staging
            __shared__ int8_t t8[128][144];
            #pragma unroll
            for (int i = 0; i < 8; i++) {
                const int row = bm + ty * 8 + i;
                const float bs = bias[row];
                #pragma unroll
                for (int j = 0; j < 8; j++) {
                    float q = rintf((acc[i][j] + bs) * invd) + zp;
                    q = fminf(fmaxf(q, 0.f), 255.f);
                    t8[tx * 8 + j][ty * 8 + i] = (int8_t)((int)q - izp);
                }
            }
            __syncthreads();
            int8_t* C = (int8_t*)Cv + (size_t)blockIdx.z * sC;
            #pragma unroll
            for (int it = 0; it < 4; it++) {
                const int l = tid + 256 * it;       // 1024 uint4 total
                const int nrow = l >> 3;
                const int seg = l & 7;
                uint4 val = *(uint4*)&t8[nrow][seg * 16];
                *(uint4*)(C + (size_t)(bn + nrow) * M + bm + seg * 16) = val;
            }
        }
    }
}

// ---------------- IMMA GEMM: C[m,n] = scale * sum_k A8[m,k] * B8[n,k] ----------------
// A: s8 row-major [M, K]; B: s8/u8 row-major [N, K]; C: f32 [M, N].
// 128x128 block tile, 8 warps (2x4), warp tile 64x32, K-step 64, double-buffered.
template<bool BU>
__global__ __launch_bounds__(256, 2) void imma_k(
    const int8_t* __restrict__ A, const void* __restrict__ Bv, float* __restrict__ C,
    int M, int N, int K, size_t sA, size_t sB, size_t sC,
    const float* __restrict__ sc1, const float* __restrict__ sc2, float fixed)
{
    const int8_t* B = (const int8_t*)Bv;
    A += (size_t)blockIdx.z * sA;
    B += (size_t)blockIdx.z * sB;
    C += (size_t)blockIdx.z * sC;
    const int bm = blockIdx.y * 128;
    const int bn = blockIdx.x * 128;
    const int tid = threadIdx.x;
    const int w = tid >> 5, lane = tid & 31;
    const int wm = w >> 2, wn = w & 3;
    const int grp = lane >> 2, tig = lane & 3;

    // padded rows: 64 data bytes + 16 pad = 80B (20 u32) -> conflict-free frag loads
    __shared__ __align__(16) char smA[2][128 * 80];
    __shared__ __align__(16) char smB[2][128 * 80];

    int acc[4][4][4];
    #pragma unroll
    for (int a = 0; a < 4; a++)
        #pragma unroll
        for (int b = 0; b < 4; b++)
            #pragma unroll
            for (int c = 0; c < 4; c++) acc[a][b][c] = 0;

    const int r0 = tid >> 2;          // 0..63
    const int sg = tid & 3;           // 16B segment
    const int8_t* Ag = A + (size_t)(bm + r0) * K + sg * 16;
    const int8_t* Bg = B + (size_t)(bn + r0) * K + sg * 16;
    const size_t rstep = (size_t)64 * K;

    uint4 pa0, pa1, pb0, pb1;
    const int nstage = K >> 6;

    // prologue: stage 0
    pa0 = *(const uint4*)(Ag);
    pa1 = *(const uint4*)(Ag + rstep);
    pb0 = *(const uint4*)(Bg);
    pb1 = *(const uint4*)(Bg + rstep);
    *(uint4*)(smA[0] + r0 * 80 + sg * 16) = pa0;
    *(uint4*)(smA[0] + (r0 + 64) * 80 + sg * 16) = pa1;
    *(uint4*)(smB[0] + r0 * 80 + sg * 16) = pb0;
    *(uint4*)(smB[0] + (r0 + 64) * 80 + sg * 16) = pb1;
    __syncthreads();

    for (int st = 0; st < nstage; st++) {
        if (st + 1 < nstage) {
            const int k0 = (st + 1) << 6;
            pa0 = *(const uint4*)(Ag + k0);
            pa1 = *(const uint4*)(Ag + rstep + k0);
            pb0 = *(const uint4*)(Bg + k0);
            pb1 = *(const uint4*)(Bg + rstep + k0);
        }
        const int buf = st & 1;
        const uint32_t* A32 = (const uint32_t*)smA[buf];
        const uint32_t* B32 = (const uint32_t*)smB[buf];
        #pragma unroll
        for (int kc = 0; kc < 2; kc++) {
            uint32_t af[4][4], bf[4][2];
            #pragma unroll
            for (int fm = 0; fm < 4; fm++) {
                const int r = wm * 64 + fm * 16 + grp;
                const uint32_t* p  = A32 + r * 20 + kc * 8 + tig;
                const uint32_t* p2 = A32 + (r + 8) * 20 + kc * 8 + tig;
                af[fm][0] = p[0];  af[fm][2] = p[4];
                af[fm][1] = p2[0]; af[fm][3] = p2[4];
            }
            #pragma unroll
            for (int fn = 0; fn < 4; fn++) {
                const int n = wn * 32 + fn * 8 + grp;
                const uint32_t* p = B32 + n * 20 + kc * 8 + tig;
                bf[fn][0] = p[0]; bf[fn][1] = p[4];
            }
            #pragma unroll
            for (int fm = 0; fm < 4; fm++)
                #pragma unroll
                for (int fn = 0; fn < 4; fn++) {
                    int* d = acc[fm][fn];
                    if (BU)
                        asm volatile(
                            "mma.sync.aligned.m16n8k32.row.col.s32.s8.u8.s32 "
                            "{%0,%1,%2,%3},{%4,%5,%6,%7},{%8,%9},{%0,%1,%2,%3};\n"
                            : "+r"(d[0]), "+r"(d[1]), "+r"(d[2]), "+r"(d[3])
                            : "r"(af[fm][0]), "r"(af[fm][1]), "r"(af[fm][2]), "r"(af[fm][3]),
                              "r"(bf[fn][0]), "r"(bf[fn][1]));
                    else
                        asm volatile(
                            "mma.sync.aligned.m16n8k32.row.col.s32.s8.s8.s32 "
                            "{%0,%1,%2,%3},{%4,%5,%6,%7},{%8,%9},{%0,%1,%2,%3};\n"
                            : "+r"(d[0]), "+r"(d[1]), "+r"(d[2]), "+r"(d[3])
                            : "r"(af[fm][0]), "r"(af[fm][1]), "r"(af[fm][2]), "r"(af[fm][3]),
                              "r"(bf[fn][0]), "r"(bf[fn][1]));
                }
        }
        if (st + 1 < nstage) {
            const int nb = (st + 1) & 1;
            *(uint4*)(smA[nb] + r0 * 80 + sg * 16) = pa0;
            *(uint4*)(smA[nb] + (r0 + 64) * 80 + sg * 16) = pa1;
            *(uint4*)(smB[nb] + r0 * 80 + sg * 16) = pb0;
            *(uint4*)(smB[nb] + (r0 + 64) * 80 + sg * 16) = pb1;
        }
        __syncthreads();
    }

    const float scale = (*sc1) * (*sc2) * fixed;
    #pragma unroll
    for (int fm = 0; fm < 4; fm++) {
        const int row = bm + wm * 64 + fm * 16 + grp;
        #pragma unroll
        for (int fn = 0; fn < 4; fn++) {
            const int col = bn + wn * 32 + fn * 8 + tig * 2;
            const int* d = acc[fm][fn];
            float2 v0 = make_float2(d[0] * scale, d[1] * scale);
            float2 v1 = make_float2(d[2] * scale, d[3] * scale);
            *(float2*)(C + (size_t)row * N + col) = v0;
            *(float2*)(C + (size_t)(row + 8) * N + col) = v1;
        }
    }
}

// ---------------- softmax + u8 quant (zp=0) ----------------
__global__ __launch_bounds__(256) void softmax_quant_k(
    const float* __restrict__ S, uint8_t* __restrict__ W8, const float* __restrict__ d_dw)
{
    const size_t rowoff = (size_t)blockIdx.x * HW;
    const float4* __restrict__ r4 = (const float4*)(S + rowoff);
    const int tid = threadIdx.x;
    float4 v[4];
    #pragma unroll
    for (int u = 0; u < 4; u++) v[u] = r4[tid * 4 + u];

    float mx = -3.0e38f;
    #pragma unroll
    for (int u = 0; u < 4; u++)
        mx = fmaxf(mx, fmaxf(fmaxf(v[u].x, v[u].y), fmaxf(v[u].z, v[u].w)));

    __shared__ float wr[8];
    __shared__ float bcast;
    for (int o = 16; o; o >>= 1) mx = fmaxf(mx, __shfl_xor_sync(0xffffffffu, mx, o));
    const int warp = tid >> 5, lane = tid & 31;
    if (lane == 0) wr[warp] = mx;
    __syncthreads();
    if (tid == 0) {
        float m = wr[0];
        #pragma unroll
        for (int i = 1; i < 8; i++) m = fmaxf(m, wr[i]);
        bcast = m;
    }
    __syncthreads();
    mx = bcast;

    float sum = 0.f;
    #pragma unroll
    for (int u = 0; u < 4; u++) {
        v[u].x = expf(v[u].x - mx);
        v[u].y = expf(v[u].y - mx);
        v[u].z = expf(v[u].z - mx);
        v[u].w = expf(v[u].w - mx);
        sum += v[u].x + v[u].y + v[u].z + v[u].w;
    }
    for (int o = 16; o; o >>= 1) sum += __shfl_xor_sync(0xffffffffu, sum, o);
    __syncthreads();
    if (lane == 0) wr[warp] = sum;
    __syncthreads();
    if (tid == 0) {
        float t = 0.f;
        #pragma unroll
        for (int i = 0; i < 8; i++) t += wr[i];
        bcast = t;
    }
    __syncthreads();
    const float inv = 1.0f / bcast;
    const float invdw = 1.0f / (*d_dw);

    uint32_t packed[4];
    #pragma unroll
    for (int u = 0; u < 4; u++) {
        const float* p = (const float*)&v[u];
        uint32_t b = 0;
        #pragma unroll
        for (int e = 0; e < 4; e++) {
            float q = fminf(fmaxf(rintf(p[e] * inv * invdw), 0.f), 255.f);
            b |= ((uint32_t)(int)q) << (e * 8);
        }
        packed[u] = b;
    }
    *(uint4*)(W8 + rowoff + tid * 16) =
        make_uint4(packed[0], packed[1], packed[2], packed[3]);
}

// ---------------- launch ----------------
extern "C" void kernel_launch(void* const* d_in, const int* in_sizes, int n_in,
                              void* d_out, int out_size)
{
    const float* x     = (const float*)d_in[0];
    const float* gamma = (const float*)d_in[1];
    const float* beta  = (const float*)d_in[2];
    const float* wq    = (const float*)d_in[3];
    const float* bq    = (const float*)d_in[4];
    const float* wk    = (const float*)d_in[5];
    const float* bk    = (const float*)d_in[6];
    const float* wv    = (const float*)d_in[7];
    const float* bv    = (const float*)d_in[8];
    const float* wp    = (const float*)d_in[9];
    const float* bp    = (const float*)d_in[10];
    const float* dq    = (const float*)d_in[11];
    const float* zq    = (const float*)d_in[12];
    const float* dk    = (const float*)d_in[13];
    const float* zk    = (const float*)d_in[14];
    const float* dv    = (const float*)d_in[15];
    const float* zv    = (const float*)d_in[16];
    const float* dw    = (const float*)d_in[17];
    float* out = (float*)d_out;

    float *hn, *h, *s;
    int8_t *q8, *k8, *v8;
    uint8_t *w8;
    cudaGetSymbolAddress((void**)&hn, g_hn);
    cudaGetSymbolAddress((void**)&h,  g_h);
    cudaGetSymbolAddress((void**)&s,  g_s);
    cudaGetSymbolAddress((void**)&q8, g_q8);
    cudaGetSymbolAddress((void**)&k8, g_k8);
    cudaGetSymbolAddress((void**)&v8, g_v8);
    cudaGetSymbolAddress((void**)&w8, g_w8);

    const size_t CS = (size_t)CC * HW;
    const size_t SS = (size_t)HW * HW;

    // 1) GroupNorm
    gn_kernel<<<BB * GROUPS, 256>>>(x, gamma, beta, hn);

    // 2) q/k/v projections -> int8 codes (q,k transposed [HW,C]; v natural [C,HW])
    dim3 gqkv(HW / 128, CC / 128, BB);
    gemm_k<1><<<gqkv, 256>>>(wq, hn, q8, CC, HW, CC, CS, CS, bq, nullptr, 0, dq, zq);
    gemm_k<1><<<gqkv, 256>>>(wk, hn, k8, CC, HW, CC, CS, CS, bk, nullptr, 0, dk, zk);
    gemm_k<2><<<gqkv, 256>>>(wv, hn, v8, CC, HW, CC, CS, CS, bv, nullptr, 0, dv, zv);

    // 3) scores S[i,j] = dq*dk*C^-0.5 * sum_c q8[i,c]*k8[j,c]   (s8 x s8 IMMA, exact)
    dim3 gsc(HW / 128, HW / 128, BB);
    imma_k<false><<<gsc, 256>>>(q8, k8, s, HW, HW, CC,
        (size_t)HW * CC, (size_t)HW * CC, SS, dq, dk, 0.044194173824159216f);

    // 4) softmax rows + u8 quant
    softmax_quant_k<<<BB * HW, 256>>>(s, w8, dw);

    // 5) h[c,q] = dv*dw * sum_j v8[c,j]*w8[q,j]   (s8 x u8 IMMA, exact)
    dim3 gvw(HW / 128, CC / 128, BB);
    imma_k<true><<<gvw, 256>>>(v8, w8, h, CC, HW, HW,
        CS, SS, CS, dv, dw, 1.0f);

    // 6) out = x + (wp @ h + bp)
    gemm_k<0><<<gqkv, 256>>>(wp, h, out, CC, HW, CC, CS, CS, bp, x, CS, nullptr, nullptr);
}

// round 4
// speedup vs baseline: 2.7906x; 1.3039x over previous
#include <cuda_runtime.h>
#include <cuda_bf16.h>
#include <stdint.h>
#include <math.h>

#define BB 4
#define CC 512
#define HW 4096
#define GROUPS 32
#define GSIZE 16

// ---------------- scratch ----------------
__device__ float   g_hn[(size_t)BB * CC * HW];
__device__ float   g_h [(size_t)BB * CC * HW];
__device__ float   g_s [(size_t)BB * HW * HW];
__device__ int8_t  g_q8[(size_t)BB * HW * CC];
__device__ int8_t  g_k8[(size_t)BB * HW * CC];
__device__ int8_t  g_v8[(size_t)BB * CC * HW];
__device__ uint8_t g_w8[(size_t)BB * HW * HW];

__device__ __forceinline__ uint32_t smem_u32(const void* p) {
    return (uint32_t)__cvta_generic_to_shared(p);
}

// split a into hi(bf16) + lo(bf16); pack pairs into u32 (low addr = low half)
__device__ __forceinline__ void split_pack2(float a0, float a1, uint32_t& hi, uint32_t& lo) {
    __nv_bfloat16 h0 = __float2bfloat16(a0);
    __nv_bfloat16 h1 = __float2bfloat16(a1);
    __nv_bfloat16 l0 = __float2bfloat16(a0 - __bfloat162float(h0));
    __nv_bfloat16 l1 = __float2bfloat16(a1 - __bfloat162float(h1));
    hi = (uint32_t)__bfloat16_as_ushort(h0) | ((uint32_t)__bfloat16_as_ushort(h1) << 16);
    lo = (uint32_t)__bfloat16_as_ushort(l0) | ((uint32_t)__bfloat16_as_ushort(l1) << 16);
}

// ---------------- GroupNorm ----------------
__global__ __launch_bounds__(256) void gn_kernel(
    const float* __restrict__ x, const float* __restrict__ gamma,
    const float* __restrict__ beta, float* __restrict__ out)
{
    const int b = blockIdx.x >> 5;
    const int g = blockIdx.x & 31;
    const size_t base = ((size_t)b * CC + (size_t)g * GSIZE) * HW;
    const int LEN4 = (GSIZE * HW) / 4;
    const float4* __restrict__ xin = (const float4*)(x + base);

    float s = 0.f, s2 = 0.f;
    for (int i = threadIdx.x; i < LEN4; i += 256) {
        float4 t = xin[i];
        s  += t.x + t.y + t.z + t.w;
        s2 += t.x * t.x + t.y * t.y + t.z * t.z + t.w * t.w;
    }
    __shared__ float wr1[8], wr2[8];
    __shared__ float s_mu, s_rstd;
    for (int o = 16; o; o >>= 1) {
        s  += __shfl_xor_sync(0xffffffffu, s,  o);
        s2 += __shfl_xor_sync(0xffffffffu, s2, o);
    }
    const int warp = threadIdx.x >> 5, lane = threadIdx.x & 31;
    if (lane == 0) { wr1[warp] = s; wr2[warp] = s2; }
    __syncthreads();
    if (threadIdx.x == 0) {
        float ts = 0.f, ts2 = 0.f;
        #pragma unroll
        for (int i = 0; i < 8; i++) { ts += wr1[i]; ts2 += wr2[i]; }
        const float inv_n = 1.0f / (float)(GSIZE * HW);
        float mu  = ts * inv_n;
        float var = ts2 * inv_n - mu * mu;
        s_mu = mu;
        s_rstd = 1.0f / sqrtf(var + 1e-6f);
    }
    __syncthreads();
    const float mu = s_mu, rstd = s_rstd;

    float4* __restrict__ o4 = (float4*)(out + base);
    for (int i = threadIdx.x; i < LEN4; i += 256) {
        float4 t = xin[i];
        const int c = g * GSIZE + ((i * 4) >> 12);
        const float ga = gamma[c] * rstd, be = beta[c];
        t.x = (t.x - mu) * ga + be;
        t.y = (t.y - mu) * ga + be;
        t.z = (t.z - mu) * ga + be;
        t.w = (t.w - mu) * ga + be;
        o4[i] = t;
    }
}

// ---------------- bf16x3 tensor-core GEMM (fp32-class precision) ----------------
// C[m,n] = A[m,k] * B[k,n].  A row-major [M,K], B row-major [K,N].
// A*B ~= Ah*Bh + Ah*Bl + Al*Bh  (bf16 mma m16n8k16, f32 accum)
// MODE 0: f32 out, += bias[row], += resid
// MODE 1: s8 out TRANSPOSED [N,M], += bias, quant codes
// MODE 2: s8 out natural [M,N],   += bias, quant codes
// 128x128 tile, 8 warps (2x4), warp tile 64x32, K-step 32, double-buffered.
#define A_ROWB 80         // 32 bf16 = 64B + 16B pad
#define B_ROWB 272        // 128 bf16 = 256B + 16B pad
#define ABYTES (128 * A_ROWB)          // 10240
#define BBYTES (32 * B_ROWB)           // 8704
#define BUFB   (2 * ABYTES + 2 * BBYTES)  // 37888
#define SMEM_BF16 (2 * BUFB)           // 75776

template<int MODE>
__global__ __launch_bounds__(256, 2) void bf16gemm_k(
    const float* __restrict__ A, const float* __restrict__ B, void* __restrict__ Cv,
    int M, int N, int K, size_t sB, size_t sC,
    const float* __restrict__ bias,
    const float* __restrict__ resid, size_t sR,
    const float* __restrict__ d_delta, const float* __restrict__ d_zp)
{
    extern __shared__ char sm[];
    const uint32_t smb = smem_u32(sm);

    const int bz = blockIdx.z;
    B += (size_t)bz * sB;
    const int bm = blockIdx.y * 128;
    const int bn = blockIdx.x * 128;
    const int tid = threadIdx.x;
    const int w = tid >> 5, lane = tid & 31;
    const int wm = w >> 2, wn = w & 3;
    const int grp = lane >> 2, tig = lane & 3;

    float acc[4][4][4];
    #pragma unroll
    for (int a = 0; a < 4; a++)
        #pragma unroll
        for (int b = 0; b < 4; b++)
            #pragma unroll
            for (int c = 0; c < 4; c++) acc[a][b][c] = 0.f;

    // gmem staging coords
    const int arow = tid >> 1, aseg = (tid & 1) * 16;   // A: 128 x 32 fl
    const int brow = tid >> 3, bseg = (tid & 7) * 16;   // B: 32 x 128 fl
    const float* Ag = A + (size_t)(bm + arow) * K + aseg;
    const float* Bg = B + (size_t)brow * N + bn + bseg;

    // per-lane ldmatrix base offsets (bytes)
    const uint32_t a_lane = (uint32_t)(lane & 15) * A_ROWB + (uint32_t)(lane >> 4) * 16;
    const uint32_t b_lane = (uint32_t)(lane & 15) * B_ROWB;

    float4 pa[4], pb[4];
    const int nst = K >> 5;   // 16

    // prologue: stage 0
    #pragma unroll
    for (int j = 0; j < 4; j++) {
        pa[j] = *(const float4*)(Ag + j * 4);
        pb[j] = *(const float4*)(Bg + j * 4);
    }
    {
        uint32_t* Ah = (uint32_t*)(sm) + arow * (A_ROWB / 4) + (aseg >> 1);
        uint32_t* Al = (uint32_t*)(sm + ABYTES) + arow * (A_ROWB / 4) + (aseg >> 1);
        uint32_t* Bh = (uint32_t*)(sm + 2 * ABYTES) + brow * (B_ROWB / 4) + (bseg >> 1);
        uint32_t* Bl = (uint32_t*)(sm + 2 * ABYTES + BBYTES) + brow * (B_ROWB / 4) + (bseg >> 1);
        #pragma unroll
        for (int j = 0; j < 4; j++) {
            uint32_t h0, l0, h1, l1;
            split_pack2(pa[j].x, pa[j].y, h0, l0);
            split_pack2(pa[j].z, pa[j].w, h1, l1);
            Ah[j * 2] = h0; Ah[j * 2 + 1] = h1;
            Al[j * 2] = l0; Al[j * 2 + 1] = l1;
            split_pack2(pb[j].x, pb[j].y, h0, l0);
            split_pack2(pb[j].z, pb[j].w, h1, l1);
            Bh[j * 2] = h0; Bh[j * 2 + 1] = h1;
            Bl[j * 2] = l0; Bl[j * 2 + 1] = l1;
        }
    }
    __syncthreads();

    for (int st = 0; st < nst; st++) {
        const bool more = (st + 1 < nst);
        if (more) {
            const int k0 = (st + 1) << 5;
            #pragma unroll
            for (int j = 0; j < 4; j++) {
                pa[j] = *(const float4*)(Ag + k0 + j * 4);
                pb[j] = *(const float4*)(Bg + (size_t)k0 * N + j * 4);
            }
        }
        const uint32_t bufo = (uint32_t)(st & 1) * BUFB;
        const uint32_t aho = smb + bufo;
        const uint32_t bho = smb + bufo + 2 * ABYTES;

        #pragma unroll
        for (int kc = 0; kc < 2; kc++) {
            // B fragments for all fn (hi & lo)
            uint32_t bhf[4][2], blf[4][2];
            #pragma unroll
            for (int fn = 0; fn < 4; fn++) {
                const uint32_t addr = bho + kc * 16 * B_ROWB + b_lane + (uint32_t)(wn * 64 + fn * 16);
                asm volatile("ldmatrix.sync.aligned.m8n8.x2.trans.shared.b16 {%0,%1},[%2];"
                             : "=r"(bhf[fn][0]), "=r"(bhf[fn][1]) : "r"(addr));
                asm volatile("ldmatrix.sync.aligned.m8n8.x2.trans.shared.b16 {%0,%1},[%2];"
                             : "=r"(blf[fn][0]), "=r"(blf[fn][1]) : "r"(addr + BBYTES));
            }
            #pragma unroll
            for (int fm = 0; fm < 4; fm++) {
                const uint32_t aaddr = aho + (uint32_t)((wm * 64 + fm * 16) * A_ROWB) + kc * 32 + a_lane;
                uint32_t ah[4], al[4];
                asm volatile("ldmatrix.sync.aligned.m8n8.x4.shared.b16 {%0,%1,%2,%3},[%4];"
                             : "=r"(ah[0]), "=r"(ah[1]), "=r"(ah[2]), "=r"(ah[3]) : "r"(aaddr));
                asm volatile("ldmatrix.sync.aligned.m8n8.x4.shared.b16 {%0,%1,%2,%3},[%4];"
                             : "=r"(al[0]), "=r"(al[1]), "=r"(al[2]), "=r"(al[3]) : "r"(aaddr + ABYTES));
                #pragma unroll
                for (int fn = 0; fn < 4; fn++) {
                    float* d = acc[fm][fn];
                    asm volatile(
                        "mma.sync.aligned.m16n8k16.row.col.f32.bf16.bf16.f32 "
                        "{%0,%1,%2,%3},{%4,%5,%6,%7},{%8,%9},{%0,%1,%2,%3};\n"
                        : "+f"(d[0]), "+f"(d[1]), "+f"(d[2]), "+f"(d[3])
                        : "r"(ah[0]), "r"(ah[1]), "r"(ah[2]), "r"(ah[3]),
                          "r"(bhf[fn][0]), "r"(bhf[fn][1]));
                    asm volatile(
                        "mma.sync.aligned.m16n8k16.row.col.f32.bf16.bf16.f32 "
                        "{%0,%1,%2,%3},{%4,%5,%6,%7},{%8,%9},{%0,%1,%2,%3};\n"
                        : "+f"(d[0]), "+f"(d[1]), "+f"(d[2]), "+f"(d[3])
                        : "r"(ah[0]), "r"(ah[1]), "r"(ah[2]), "r"(ah[3]),
                          "r"(blf[fn][0]), "r"(blf[fn][1]));
                    asm volatile(
                        "mma.sync.aligned.m16n8k16.row.col.f32.bf16.bf16.f32 "
                        "{%0,%1,%2,%3},{%4,%5,%6,%7},{%8,%9},{%0,%1,%2,%3};\n"
                        : "+f"(d[0]), "+f"(d[1]), "+f"(d[2]), "+f"(d[3])
                        : "r"(al[0]), "r"(al[1]), "r"(al[2]), "r"(al[3]),
                          "r"(bhf[fn][0]), "r"(bhf[fn][1]));
                }
            }
        }
        if (more) {
            const uint32_t nb = (uint32_t)((st + 1) & 1) * BUFB;
            char* base = sm + nb;
            uint32_t* Ah = (uint32_t*)(base) + arow * (A_ROWB / 4) + (aseg >> 1);
            uint32_t* Al = (uint32_t*)(base + ABYTES) + arow * (A_ROWB / 4) + (aseg >> 1);
            uint32_t* Bh = (uint32_t*)(base + 2 * ABYTES) + brow * (B_ROWB / 4) + (bseg >> 1);
            uint32_t* Bl = (uint32_t*)(base + 2 * ABYTES + BBYTES) + brow * (B_ROWB / 4) + (bseg >> 1);
            #pragma unroll
            for (int j = 0; j < 4; j++) {
                uint32_t h0, l0, h1, l1;
                split_pack2(pa[j].x, pa[j].y, h0, l0);
                split_pack2(pa[j].z, pa[j].w, h1, l1);
                Ah[j * 2] = h0; Ah[j * 2 + 1] = h1;
                Al[j * 2] = l0; Al[j * 2 + 1] = l1;
                split_pack2(pb[j].x, pb[j].y, h0, l0);
                split_pack2(pb[j].z, pb[j].w, h1, l1);
                Bh[j * 2] = h0; Bh[j * 2 + 1] = h1;
                Bl[j * 2] = l0; Bl[j * 2 + 1] = l1;
            }
        }
        __syncthreads();
    }

    if (MODE == 0) {
        float* C = (float*)Cv + (size_t)bz * sC;
        const float* R = resid + (size_t)bz * sR;
        #pragma unroll
        for (int fm = 0; fm < 4; fm++) {
            const int r1 = wm * 64 + fm * 16 + grp;
            const int r2 = r1 + 8;
            const float b1v = bias[bm + r1];
            const float b2v = bias[bm + r2];
            #pragma unroll
            for (int fn = 0; fn < 4; fn++) {
                const int c = wn * 32 + fn * 8 + tig * 2;
                const float* d = acc[fm][fn];
                float2 rr1 = *(const float2*)(R + (size_t)(bm + r1) * N + bn + c);
                float2 rr2 = *(const float2*)(R + (size_t)(bm + r2) * N + bn + c);
                float2 o1 = make_float2(d[0] + b1v + rr1.x, d[1] + b1v + rr1.y);
                float2 o2 = make_float2(d[2] + b2v + rr2.x, d[3] + b2v + rr2.y);
                *(float2*)(C + (size_t)(bm + r1) * N + bn + c) = o1;
                *(float2*)(C + (size_t)(bm + r2) * N + bn + c) = o2;
            }
        }
    } else {
        const float delta = *d_delta;
        const float zp = *d_zp;
        const float invd = 1.0f / delta;
        const int izp = (int)rintf(zp);
        char* t8 = sm;   // 128x144 staging; mainloop done for all warps

        #pragma unroll
        for (int fm = 0; fm < 4; fm++) {
            const int r1 = wm * 64 + fm * 16 + grp;
            const int r2 = r1 + 8;
            const float b1v = bias[bm + r1];
            const float b2v = bias[bm + r2];
            #pragma unroll
            for (int fn = 0; fn < 4; fn++) {
                const int c = wn * 32 + fn * 8 + tig * 2;
                const float* d = acc[fm][fn];
                int8_t q[4];
                #pragma unroll
                for (int e = 0; e < 4; e++) {
                    const float v = d[e] + ((e < 2) ? b1v : b2v);
                    float qq = rintf(v * invd) + zp;
                    qq = fminf(fmaxf(qq, 0.f), 255.f);
                    q[e] = (int8_t)((int)qq - izp);
                }
                if (MODE == 2) {
                    t8[r1 * 144 + c] = q[0]; t8[r1 * 144 + c + 1] = q[1];
                    t8[r2 * 144 + c] = q[2]; t8[r2 * 144 + c + 1] = q[3];
                } else {
                    t8[c * 144 + r1] = q[0]; t8[(c + 1) * 144 + r1] = q[1];
                    t8[c * 144 + r2] = q[2]; t8[(c + 1) * 144 + r2] = q[3];
                }
            }
        }
        __syncthreads();
        int8_t* C = (int8_t*)Cv + (size_t)bz * sC;
        #pragma unroll
        for (int it = 0; it < 4; it++) {
            const int l = tid + 256 * it;
            const int row = l >> 3;
            const int seg = l & 7;
            uint4 val = *(uint4*)&t8[row * 144 + seg * 16];
            if (MODE == 2)
                *(uint4*)(C + (size_t)(bm + row) * N + bn + seg * 16) = val;
            else
                *(uint4*)(C + (size_t)(bn + row) * M + bm + seg * 16) = val;
        }
    }
}

// ---------------- IMMA GEMM (s8 x s8/u8, exact) ----------------
template<bool BU>
__global__ __launch_bounds__(256, 2) void imma_k(
    const int8_t* __restrict__ A, const void* __restrict__ Bv, float* __restrict__ C,
    int M, int N, int K, size_t sA, size_t sB, size_t sC,
    const float* __restrict__ sc1, const float* __restrict__ sc2, float fixed)
{
    const int8_t* B = (const int8_t*)Bv;
    A += (size_t)blockIdx.z * sA;
    B += (size_t)blockIdx.z * sB;
    C += (size_t)blockIdx.z * sC;
    const int bm = blockIdx.y * 128;
    const int bn = blockIdx.x * 128;
    const int tid = threadIdx.x;
    const int w = tid >> 5, lane = tid & 31;
    const int wm = w >> 2, wn = w & 3;
    const int grp = lane >> 2, tig = lane & 3;

    __shared__ __align__(16) char smA[2][128 * 80];
    __shared__ __align__(16) char smB[2][128 * 80];

    int acc[4][4][4];
    #pragma unroll
    for (int a = 0; a < 4; a++)
        #pragma unroll
        for (int b = 0; b < 4; b++)
            #pragma unroll
            for (int c = 0; c < 4; c++) acc[a][b][c] = 0;

    const int r0 = tid >> 2;
    const int sg = tid & 3;
    const int8_t* Ag = A + (size_t)(bm + r0) * K + sg * 16;
    const int8_t* Bg = B + (size_t)(bn + r0) * K + sg * 16;
    const size_t rstep = (size_t)64 * K;

    uint4 pa0, pa1, pb0, pb1;
    const int nstage = K >> 6;

    pa0 = *(const uint4*)(Ag);
    pa1 = *(const uint4*)(Ag + rstep);
    pb0 = *(const uint4*)(Bg);
    pb1 = *(const uint4*)(Bg + rstep);
    *(uint4*)(smA[0] + r0 * 80 + sg * 16) = pa0;
    *(uint4*)(smA[0] + (r0 + 64) * 80 + sg * 16) = pa1;
    *(uint4*)(smB[0] + r0 * 80 + sg * 16) = pb0;
    *(uint4*)(smB[0] + (r0 + 64) * 80 + sg * 16) = pb1;
    __syncthreads();

    for (int st = 0; st < nstage; st++) {
        if (st + 1 < nstage) {
            const int k0 = (st + 1) << 6;
            pa0 = *(const uint4*)(Ag + k0);
            pa1 = *(const uint4*)(Ag + rstep + k0);
            pb0 = *(const uint4*)(Bg + k0);
            pb1 = *(const uint4*)(Bg + rstep + k0);
        }
        const int buf = st & 1;
        const uint32_t* A32 = (const uint32_t*)smA[buf];
        const uint32_t* B32 = (const uint32_t*)smB[buf];
        #pragma unroll
        for (int kc = 0; kc < 2; kc++) {
            uint32_t af[4][4], bf[4][2];
            #pragma unroll
            for (int fm = 0; fm < 4; fm++) {
                const int r = wm * 64 + fm * 16 + grp;
                const uint32_t* p  = A32 + r * 20 + kc * 8 + tig;
                const uint32_t* p2 = A32 + (r + 8) * 20 + kc * 8 + tig;
                af[fm][0] = p[0];  af[fm][2] = p[4];
                af[fm][1] = p2[0]; af[fm][3] = p2[4];
            }
            #pragma unroll
            for (int fn = 0; fn < 4; fn++) {
                const int n = wn * 32 + fn * 8 + grp;
                const uint32_t* p = B32 + n * 20 + kc * 8 + tig;
                bf[fn][0] = p[0]; bf[fn][1] = p[4];
            }
            #pragma unroll
            for (int fm = 0; fm < 4; fm++)
                #pragma unroll
                for (int fn = 0; fn < 4; fn++) {
                    int* d = acc[fm][fn];
                    if (BU)
                        asm volatile(
                            "mma.sync.aligned.m16n8k32.row.col.s32.s8.u8.s32 "
                            "{%0,%1,%2,%3},{%4,%5,%6,%7},{%8,%9},{%0,%1,%2,%3};\n"
                            : "+r"(d[0]), "+r"(d[1]), "+r"(d[2]), "+r"(d[3])
                            : "r"(af[fm][0]), "r"(af[fm][1]), "r"(af[fm][2]), "r"(af[fm][3]),
                              "r"(bf[fn][0]), "r"(bf[fn][1]));
                    else
                        asm volatile(
                            "mma.sync.aligned.m16n8k32.row.col.s32.s8.s8.s32 "
                            "{%0,%1,%2,%3},{%4,%5,%6,%7},{%8,%9},{%0,%1,%2,%3};\n"
                            : "+r"(d[0]), "+r"(d[1]), "+r"(d[2]), "+r"(d[3])
                            : "r"(af[fm][0]), "r"(af[fm][1]), "r"(af[fm][2]), "r"(af[fm][3]),
                              "r"(bf[fn][0]), "r"(bf[fn][1]));
                }
        }
        if (st + 1 < nstage) {
            const int nb = (st + 1) & 1;
            *(uint4*)(smA[nb] + r0 * 80 + sg * 16) = pa0;
            *(uint4*)(smA[nb] + (r0 + 64) * 80 + sg * 16) = pa1;
            *(uint4*)(smB[nb] + r0 * 80 + sg * 16) = pb0;
            *(uint4*)(smB[nb] + (r0 + 64) * 80 + sg * 16) = pb1;
        }
        __syncthreads();
    }

    const float scale = (*sc1) * (*sc2) * fixed;
    #pragma unroll
    for (int fm = 0; fm < 4; fm++) {
        const int row = bm + wm * 64 + fm * 16 + grp;
        #pragma unroll
        for (int fn = 0; fn < 4; fn++) {
            const int col = bn + wn * 32 + fn * 8 + tig * 2;
            const int* d = acc[fm][fn];
            float2 v0 = make_float2(d[0] * scale, d[1] * scale);
            float2 v1 = make_float2(d[2] * scale, d[3] * scale);
            *(float2*)(C + (size_t)row * N + col) = v0;
            *(float2*)(C + (size_t)(row + 8) * N + col) = v1;
        }
    }
}

// ---------------- softmax + u8 quant (zp=0) ----------------
__global__ __launch_bounds__(256) void softmax_quant_k(
    const float* __restrict__ S, uint8_t* __restrict__ W8, const float* __restrict__ d_dw)
{
    const size_t rowoff = (size_t)blockIdx.x * HW;
    const float4* __restrict__ r4 = (const float4*)(S + rowoff);
    const int tid = threadIdx.x;
    float4 v[4];
    #pragma unroll
    for (int u = 0; u < 4; u++) v[u] = r4[tid * 4 + u];

    float mx = -3.0e38f;
    #pragma unroll
    for (int u = 0; u < 4; u++)
        mx = fmaxf(mx, fmaxf(fmaxf(v[u].x, v[u].y), fmaxf(v[u].z, v[u].w)));

    __shared__ float wr[8];
    __shared__ float bcast;
    for (int o = 16; o; o >>= 1) mx = fmaxf(mx, __shfl_xor_sync(0xffffffffu, mx, o));
    const int warp = tid >> 5, lane = tid & 31;
    if (lane == 0) wr[warp] = mx;
    __syncthreads();
    if (tid == 0) {
        float m = wr[0];
        #pragma unroll
        for (int i = 1; i < 8; i++) m = fmaxf(m, wr[i]);
        bcast = m;
    }
    __syncthreads();
    mx = bcast;

    float sum = 0.f;
    #pragma unroll
    for (int u = 0; u < 4; u++) {
        v[u].x = expf(v[u].x - mx);
        v[u].y = expf(v[u].y - mx);
        v[u].z = expf(v[u].z - mx);
        v[u].w = expf(v[u].w - mx);
        sum += v[u].x + v[u].y + v[u].z + v[u].w;
    }
    for (int o = 16; o; o >>= 1) sum += __shfl_xor_sync(0xffffffffu, sum, o);
    __syncthreads();
    if (lane == 0) wr[warp] = sum;
    __syncthreads();
    if (tid == 0) {
        float t = 0.f;
        #pragma unroll
        for (int i = 0; i < 8; i++) t += wr[i];
        bcast = t;
    }
    __syncthreads();
    const float inv = 1.0f / bcast;
    const float invdw = 1.0f / (*d_dw);

    uint32_t packed[4];
    #pragma unroll
    for (int u = 0; u < 4; u++) {
        const float* p = (const float*)&v[u];
        uint32_t b = 0;
        #pragma unroll
        for (int e = 0; e < 4; e++) {
            float q = fminf(fmaxf(rintf(p[e] * inv * invdw), 0.f), 255.f);
            b |= ((uint32_t)(int)q) << (e * 8);
        }
        packed[u] = b;
    }
    *(uint4*)(W8 + rowoff + tid * 16) =
        make_uint4(packed[0], packed[1], packed[2], packed[3]);
}

// ---------------- launch ----------------
extern "C" void kernel_launch(void* const* d_in, const int* in_sizes, int n_in,
                              void* d_out, int out_size)
{
    const float* x     = (const float*)d_in[0];
    const float* gamma = (const float*)d_in[1];
    const float* beta  = (const float*)d_in[2];
    const float* wq    = (const float*)d_in[3];
    const float* bq    = (const float*)d_in[4];
    const float* wk    = (const float*)d_in[5];
    const float* bk    = (const float*)d_in[6];
    const float* wv    = (const float*)d_in[7];
    const float* bv    = (const float*)d_in[8];
    const float* wp    = (const float*)d_in[9];
    const float* bp    = (const float*)d_in[10];
    const float* dq    = (const float*)d_in[11];
    const float* zq    = (const float*)d_in[12];
    const float* dk    = (const float*)d_in[13];
    const float* zk    = (const float*)d_in[14];
    const float* dv    = (const float*)d_in[15];
    const float* zv    = (const float*)d_in[16];
    const float* dw    = (const float*)d_in[17];
    float* out = (float*)d_out;

    float *hn, *h, *s;
    int8_t *q8, *k8, *v8;
    uint8_t *w8;
    cudaGetSymbolAddress((void**)&hn, g_hn);
    cudaGetSymbolAddress((void**)&h,  g_h);
    cudaGetSymbolAddress((void**)&s,  g_s);
    cudaGetSymbolAddress((void**)&q8, g_q8);
    cudaGetSymbolAddress((void**)&k8, g_k8);
    cudaGetSymbolAddress((void**)&v8, g_v8);
    cudaGetSymbolAddress((void**)&w8, g_w8);

    cudaFuncSetAttribute(bf16gemm_k<0>, cudaFuncAttributeMaxDynamicSharedMemorySize, SMEM_BF16);
    cudaFuncSetAttribute(bf16gemm_k<1>, cudaFuncAttributeMaxDynamicSharedMemorySize, SMEM_BF16);
    cudaFuncSetAttribute(bf16gemm_k<2>, cudaFuncAttributeMaxDynamicSharedMemorySize, SMEM_BF16);

    const size_t CS = (size_t)CC * HW;
    const size_t SS = (size_t)HW * HW;

    // 1) GroupNorm
    gn_kernel<<<BB * GROUPS, 256>>>(x, gamma, beta, hn);

    // 2) q/k/v projections (bf16x3 tensor cores) -> int8 codes
    dim3 gqkv(HW / 128, CC / 128, BB);
    bf16gemm_k<1><<<gqkv, 256, SMEM_BF16>>>(wq, hn, q8, CC, HW, CC, CS, (size_t)HW * CC, bq, nullptr, 0, dq, zq);
    bf16gemm_k<1><<<gqkv, 256, SMEM_BF16>>>(wk, hn, k8, CC, HW, CC, CS, (size_t)HW * CC, bk, nullptr, 0, dk, zk);
    bf16gemm_k<2><<<gqkv, 256, SMEM_BF16>>>(wv, hn, v8, CC, HW, CC, CS, CS, bv, nullptr, 0, dv, zv);

    // 3) scores (s8 x s8 IMMA, exact)
    dim3 gsc(HW / 128, HW / 128, BB);
    imma_k<false><<<gsc, 256>>>(q8, k8, s, HW, HW, CC,
        (size_t)HW * CC, (size_t)HW * CC, SS, dq, dk, 0.044194173824159216f);

    // 4) softmax rows + u8 quant
    softmax_quant_k<<<BB * HW, 256>>>(s, w8, dw);

    // 5) h = v8 @ w8^T (s8 x u8 IMMA, exact)
    dim3 gvw(HW / 128, CC / 128, BB);
    imma_k<true><<<gvw, 256>>>(v8, w8, h, CC, HW, HW, CS, SS, CS, dv, dw, 1.0f);

    // 6) out = x + (wp @ h + bp)  (bf16x3 tensor cores)
    bf16gemm_k<0><<<gqkv, 256, SMEM_BF16>>>(wp, h, out, CC, HW, CC, CS, CS, bp, x, CS, nullptr, nullptr);
}